// round 2
// baseline (speedup 1.0000x reference)
#include <cuda_runtime.h>
#include <math.h>

#define EPS_F 1e-4f
#define NEG_BIG (-3.0e38f)

// Scratch: lmax (max over 4 class logits) per level, layout (B, A, D, H, W)
__device__ __align__(16) float g_lmax0[4194304]; // 2*2*64*128*128
__device__ __align__(16) float g_lmax1[524288];  // 2*2*32*64*64

__device__ __forceinline__ float clipsig(float x) {
    float s = 1.0f / (1.0f + expf(-x));
    return fminf(fmaxf(s, EPS_F), 1.0f - EPS_F);
}
__device__ __forceinline__ float softplusf(float x) {
    return (x > 0.0f) ? (x + log1pf(expf(-x))) : log1pf(expf(x));
}

__global__ void zero_out_k(float* out, int n) {
    int i = blockIdx.x * blockDim.x + threadIdx.x;
    if (i < n) out[i] = 0.0f;
}

// ---------------- Pass 1: lmax[b,a,d,h,w] = max_c logits[b, c*A+a, d,h,w] -------------
// logits element index = (b*4 + c)*M + rem  where M = A*D*H*W, rem = a*DHW + spatial.
template<int LVL>
__global__ void pass1_k(const float4* __restrict__ lg, int log2M4, int n4) {
    int i = blockIdx.x * blockDim.x + threadIdx.x;
    if (i >= n4) return;
    int b   = i >> log2M4;
    int rem = i & ((1 << log2M4) - 1);
    int M4  = 1 << log2M4;
    int base = ((b << 2) << log2M4) + rem;
    float4 v0 = __ldg(&lg[base]);
    float4 v1 = __ldg(&lg[base + M4]);
    float4 v2 = __ldg(&lg[base + 2 * M4]);
    float4 v3 = __ldg(&lg[base + 3 * M4]);
    float4 m;
    m.x = fmaxf(fmaxf(v0.x, v1.x), fmaxf(v2.x, v3.x));
    m.y = fmaxf(fmaxf(v0.y, v1.y), fmaxf(v2.y, v3.y));
    m.z = fmaxf(fmaxf(v0.z, v1.z), fmaxf(v2.z, v3.z));
    m.w = fmaxf(fmaxf(v0.w, v1.w), fmaxf(v2.w, v3.w));
    float4* dst = (float4*)(LVL ? g_lmax1 : g_lmax0);
    dst[i] = m;
}

// ---------------- Pass 2: local-max filter + reduction (logit domain) -----------------
template<int D, int H, int W, int TD, int TH, int LVL>
__global__ void pass2_k(float* __restrict__ out) {
    constexpr int W4 = W / 4;
    constexpr int HR = TH + 2, DR = TD + 2;
    __shared__ float s[DR * HR * W];
    __shared__ float rl[8], rc[8];

    const float* lmax = LVL ? g_lmax1 : g_lmax0;
    int bz = blockIdx.z;                       // b*A + a
    int d0 = blockIdx.y * TD, h0 = blockIdx.x * TH;
    const float4* base4 = (const float4*)(lmax + (size_t)bz * D * H * W);
    int tid = threadIdx.x;

    // Cooperative halo tile load (out-of-bounds rows -> -inf padding)
    constexpr int TOT4 = DR * HR * W4;
    for (int j = tid; j < TOT4; j += blockDim.x) {
        int wv  = j % W4;
        int row = j / W4;
        int hh = row % HR;
        int dd = row / HR;
        int d = d0 + dd - 1, h = h0 + hh - 1;
        float4 v;
        if ((unsigned)d < (unsigned)D && (unsigned)h < (unsigned)H)
            v = __ldg(&base4[(d * H + h) * W4 + wv]);
        else
            v = make_float4(NEG_BIG, NEG_BIG, NEG_BIG, NEG_BIG);
        reinterpret_cast<float4*>(s)[row * W4 + wv] = v;
    }
    __syncthreads();

    float lsum = 0.0f, csum = 0.0f;
    constexpr int NCH = TD * TH * W4;
    for (int c = tid; c < NCH; c += blockDim.x) {
        int wv = c % W4;
        int hh = (c / W4) % TH;
        int dd = c / (W4 * TH);
        float p0 = NEG_BIG, p1 = NEG_BIG, p2 = NEG_BIG, p3 = NEG_BIG;
        float c0 = 0.f, c1 = 0.f, c2 = 0.f, c3 = 0.f;
        #pragma unroll
        for (int zz = 0; zz < 3; zz++) {
            #pragma unroll
            for (int yy = 0; yy < 3; yy++) {
                const float* row = &s[((dd + zz) * HR + (hh + yy)) * W];
                float4 v = reinterpret_cast<const float4*>(row)[wv];
                float L = (wv > 0)      ? row[wv * 4 - 1] : NEG_BIG;
                float R = (wv < W4 - 1) ? row[wv * 4 + 4] : NEG_BIG;
                p0 = fmaxf(p0, fmaxf(L,   fmaxf(v.x, v.y)));
                p1 = fmaxf(p1, fmaxf(v.x, fmaxf(v.y, v.z)));
                p2 = fmaxf(p2, fmaxf(v.y, fmaxf(v.z, v.w)));
                p3 = fmaxf(p3, fmaxf(v.z, fmaxf(v.w, R)));
                if (zz == 1 && yy == 1) { c0 = v.x; c1 = v.y; c2 = v.z; c3 = v.w; }
            }
        }
        #define DO_ONE(CC, PP)                                            \
            if ((PP) == (CC)) {                                           \
                float pr = clipsig(CC);                                   \
                if (pr > EPS_F) { lsum += logf(1.0f - pr) * pr; csum += pr; } \
            }
        DO_ONE(c0, p0) DO_ONE(c1, p1) DO_ONE(c2, p2) DO_ONE(c3, p3)
        #undef DO_ONE
    }

    // block reduce
    #pragma unroll
    for (int o = 16; o; o >>= 1) {
        lsum += __shfl_down_sync(0xffffffffu, lsum, o);
        csum += __shfl_down_sync(0xffffffffu, csum, o);
    }
    int wid = tid >> 5, lid = tid & 31;
    if (lid == 0) { rl[wid] = lsum; rc[wid] = csum; }
    __syncthreads();
    if (tid == 0) {
        float L = 0.f, C = 0.f;
        #pragma unroll
        for (int i = 0; i < 8; i++) { L += rl[i]; C += rc[i]; }
        atomicAdd(&out[1], -L);  // loss_neg = -sum(log(1-p)*p)
        atomicAdd(&out[4], C);   // count_neg
    }
}

// ---------------- Points kernel: pos/other losses + negmask correction ----------------
__global__ void points_k(const float* __restrict__ lg0, const float* __restrict__ lg1,
                         const float* __restrict__ gt0, const float* __restrict__ gt1,
                         const int* __restrict__ co0, const int* __restrict__ co1,
                         const float* __restrict__ wcls, float* __restrict__ out) {
    int tid = threadIdx.x;        // 128 threads: (level, b, k)
    int level = tid >> 6;
    int b = (tid >> 5) & 1;
    int k = tid & 31;

    int D = level ? 32 : 64, H = level ? 64 : 128, W = level ? 64 : 128;
    const int A = 2;
    int DHW = D * H * W;
    const float* lg   = level ? lg1 : lg0;
    const float* gt   = level ? gt1 : gt0;
    const int*   co   = level ? co1 : co0;
    const float* lmax = level ? g_lmax1 : g_lmax0;

    __shared__ int   present[2][2][4];
    __shared__ int   voxkey[128];
    __shared__ float acc[6];
    if (tid < 6)  acc[tid] = 0.0f;
    if (tid < 16) ((int*)present)[tid] = 0;
    __syncthreads();

    const int* c = &co[(b * 32 + k) * 4];
    int a0 = c[0], d1 = c[1], h1 = c[2], w1 = c[3];
    bool valid = (a0 > -1);
    int a = valid ? a0 : 0, d = valid ? d1 : 0, h = valid ? h1 : 0, w = valid ? w1 : 0;
    int sp = (d * H + h) * W + w;

    float gv = gt[(b * A + a) * DHW + sp];
    int cls = (int)gv - 1;
    cls = min(max(cls, 0), 3);
    float vm = valid ? 1.0f : 0.0f;

    float l[4], p[4];
    #pragma unroll
    for (int cc = 0; cc < 4; cc++) {
        l[cc] = lg[(b * 8 + cc * 2 + a) * DHW + sp];
        p[cc] = clipsig(l[cc]);
    }
    float pt = p[cls], lt = l[cls];
    float wpos = (1.0f - pt) * wcls[cls] * vm;
    float lpos = softplusf(-lt) * wpos;   // -log_sigmoid(l_t)*w_pos

    if (valid) present[level][b][cls] = 1;
    voxkey[tid] = valid ? (((a * D + d) * H + h) * W + w) : -1;
    __syncthreads();

    float loth = 0.0f, coth = 0.0f;
    #pragma unroll
    for (int cc = 0; cc < 4; cc++) {
        float wo = fmaxf(p[cc] - (pt - 0.05f), 0.0f);
        wo *= (p[cc] > 0.5f) ? 1.0f : 0.0f;
        wo *= (pt   > 0.5f) ? 1.0f : 0.0f;
        wo *= (1.0f - (float)present[level][b][cc]) * vm;
        loth += softplusf(l[cc]) * wo;    // -log_sigmoid(-l)*w_o
        coth += wo;
    }

    // negmask correction: subtract the dense-sum contribution of coord voxels
    float corr_l = 0.0f, corr_c = 0.0f;
    if (valid) {
        bool first = true;
        int gbase = tid - k;
        int mykey = voxkey[tid];
        for (int kk = 0; kk < k; kk++)
            if (voxkey[gbase + kk] == mykey) { first = false; break; }
        if (first) {
            int vbase = (b * A + a) * DHW;
            float cl = lmax[vbase + sp];
            float pooled = cl;
            for (int zz = -1; zz <= 1; zz++)
                for (int yy = -1; yy <= 1; yy++)
                    for (int xx = -1; xx <= 1; xx++) {
                        int dd = d + zz, hh = h + yy, ww = w + xx;
                        if ((unsigned)dd < (unsigned)D && (unsigned)hh < (unsigned)H &&
                            (unsigned)ww < (unsigned)W)
                            pooled = fmaxf(pooled, lmax[vbase + (dd * H + hh) * W + ww]);
                    }
            if (pooled == cl) {
                float pr = clipsig(cl);
                if (pr > EPS_F) { corr_l = logf(1.0f - pr) * pr; corr_c = -pr; }
            }
        }
    }

    atomicAdd(&acc[0], lpos);
    atomicAdd(&acc[3], wpos);
    atomicAdd(&acc[2], loth);
    atomicAdd(&acc[5], coth);
    atomicAdd(&acc[1], corr_l);  // loss_neg had -sum over ALL; add back +log(1-p)*p at points
    atomicAdd(&acc[4], corr_c);  // count_neg: remove p at points
    __syncthreads();
    if (tid < 6) atomicAdd(&out[tid], acc[tid]);
}

extern "C" void kernel_launch(void* const* d_in, const int* in_sizes, int n_in,
                              void* d_out, int out_size) {
    // setup_inputs() insertion order: logits0, gtprob0, coords0, logits1, gtprob1, coords1, weight_cls
    const float* lg0 = (const float*)d_in[0];
    const float* gt0 = (const float*)d_in[1];
    const int*   co0 = (const int*)d_in[2];
    const float* lg1 = (const float*)d_in[3];
    const float* gt1 = (const float*)d_in[4];
    const int*   co1 = (const int*)d_in[5];
    const float* wc  = (const float*)d_in[6];
    float* out = (float*)d_out;

    zero_out_k<<<1, 256>>>(out, out_size);

    // Level 0: B=2, A=2, D=64, H=128, W=128 -> M4 = 2^19, n4 = 1048576
    pass1_k<0><<<4096, 256>>>((const float4*)lg0, 19, 1048576);
    // Level 1: B=2, A=2, D=32, H=64, W=64 -> M4 = 2^16, n4 = 131072
    pass1_k<1><<<512, 256>>>((const float4*)lg1, 16, 131072);

    dim3 g0(128 / 8, 64 / 4, 4);   // (16, 16, 4)
    pass2_k<64, 128, 128, 4, 8, 0><<<g0, 256>>>(out);
    dim3 g1(64 / 8, 32 / 4, 4);    // (8, 8, 4)
    pass2_k<32, 64, 64, 4, 8, 1><<<g1, 256>>>(out);

    points_k<<<1, 128>>>(lg0, lg1, gt0, gt1, co0, co1, wc, out);
}